// round 10
// baseline (speedup 1.0000x reference)
#include <cuda_runtime.h>
#include <cuda_bf16.h>
#include <cstdint>

// Problem constants (match reference)
#define NGRID        512
#define X0_C         1.0f
#define XMAX_C       10.0f
#define DX_C         ((XMAX_C - X0_C) / (float)(NGRID - 1))   // 9/511
#define N_BOND_TYPES 10
#define NUM_INGRLS   16
#define E_MAX        2000000

#define TRANS_BLOCKS 320          // 163840 elems / 512
#define HIST_BLOCKS  592
#define EPB          2048         // edges per chunk
#define MAX_CHUNKS   (E_MAX / EPB + N_BOND_TYPES + 4)   // 990

#define SLICE_ELEMS  (NGRID * NUM_INGRLS)               // 8192 floats = 32KB
#define SMEM_BYTES   (2 * SLICE_ELEMS * sizeof(float))  // 64KB

// Transposed tables: [B][G][16] -> one (b,i0) row = 64B contiguous.
__device__ float g_hopT[N_BOND_TYPES * SLICE_ELEMS];
__device__ float g_ovlT[N_BOND_TYPES * SLICE_ELEMS];

// Binning state + sorted edge records: (e | type<<24, rij_bits)
__device__ int  g_hist[N_BOND_TYPES];      // zero-init; re-zeroed by K2 each run
__device__ int  g_cursor[N_BOND_TYPES];
__device__ int2 g_sorted[E_MAX];
__device__ int4 g_chunks[MAX_CHUNKS];      // (type, start_pos, count, 0)

// ---------------------------------------------------------------------------
// K1: table transpose (blocks [0,320)) + edge-type histogram (rest)
// ---------------------------------------------------------------------------
__global__ void __launch_bounds__(256) k1_transpose_hist(
    const float* __restrict__ hopping_tables,
    const float* __restrict__ overlap_tables,
    const int*   __restrict__ edge_type,
    int n_edges)
{
    if (blockIdx.x < TRANS_BLOCKS) {
        int idx = blockIdx.x * blockDim.x + threadIdx.x;
        const int total = N_BOND_TYPES * NUM_INGRLS * NGRID;
        if (idx >= total) return;
        int g  = idx & (NGRID - 1);
        int bm = idx >> 9;
        int m  = bm & (NUM_INGRLS - 1);
        int b  = bm >> 4;
        int dst = (b * NGRID + g) * NUM_INGRLS + m;
        g_hopT[dst] = hopping_tables[idx];
        g_ovlT[dst] = overlap_tables[idx];
    } else {
        __shared__ int s_cnt[N_BOND_TYPES];
        if (threadIdx.x < N_BOND_TYPES) s_cnt[threadIdx.x] = 0;
        __syncthreads();
        int nb = gridDim.x - TRANS_BLOCKS;
        int start = (blockIdx.x - TRANS_BLOCKS) * 256 + threadIdx.x;
        int stride = nb * 256;
        for (int e = start; e < n_edges; e += stride) {
            int t = __ldg(&edge_type[e]);
            atomicAdd(&s_cnt[t], 1);
        }
        __syncthreads();
        if (threadIdx.x < N_BOND_TYPES && s_cnt[threadIdx.x] != 0)
            atomicAdd(&g_hist[threadIdx.x], s_cnt[threadIdx.x]);
    }
}

// ---------------------------------------------------------------------------
// K2: warp scan of histogram -> bin cursors + per-(type,chunk) descriptors.
// Also re-zeroes the histogram for the next graph replay.
// ---------------------------------------------------------------------------
__global__ void k2_scan_chunks(int max_chunks)
{
    int lane = threadIdx.x;   // 32 threads
    int cnt = (lane < N_BOND_TYPES) ? g_hist[lane] : 0;

    // inclusive scan of counts
    int s = cnt;
    #pragma unroll
    for (int d = 1; d < 32; d <<= 1) {
        int v = __shfl_up_sync(0xFFFFFFFFu, s, d);
        if (lane >= d) s += v;
    }
    int start = s - cnt;
    if (lane < N_BOND_TYPES) {
        g_cursor[lane] = start;
        g_hist[lane] = 0;
    }

    // inclusive scan of chunk counts
    int nch = (cnt + EPB - 1) / EPB;
    int cs = nch;
    #pragma unroll
    for (int d = 1; d < 32; d <<= 1) {
        int v = __shfl_up_sync(0xFFFFFFFFu, cs, d);
        if (lane >= d) cs += v;
    }
    int chunk_base = cs - nch;
    int total_chunks = __shfl_sync(0xFFFFFFFFu, cs, 31);

    if (lane < N_BOND_TYPES) {
        for (int c = 0; c < nch; c++) {
            int4 d4;
            d4.x = lane;
            d4.y = start + c * EPB;
            d4.z = min(EPB, cnt - c * EPB);
            d4.w = 0;
            g_chunks[chunk_base + c] = d4;
        }
    }
    for (int i = total_chunks + lane; i < max_chunks; i += 32)
        g_chunks[i] = make_int4(-1, 0, 0, 0);
}

// ---------------------------------------------------------------------------
// K3: counting-sort scatter. One global atomic per (block,type); records
// (e|t<<24, rij_bits). Order within a bin is non-deterministic but every
// edge writes its own output slot later -> output deterministic.
// ---------------------------------------------------------------------------
__global__ void __launch_bounds__(256) k3_scatter(
    const float* __restrict__ rij,
    const int*   __restrict__ edge_type,
    int n_edges)
{
    __shared__ int s_cnt[N_BOND_TYPES];
    __shared__ int s_base[N_BOND_TYPES];
    if (threadIdx.x < N_BOND_TYPES) s_cnt[threadIdx.x] = 0;
    __syncthreads();

    const int PER_THREAD = EPB / 256;   // 8
    int base_e = blockIdx.x * EPB;

    int   t_j[PER_THREAD];
    int   rank_j[PER_THREAD];
    int   e_j[PER_THREAD];
    float r_j[PER_THREAD];

    #pragma unroll
    for (int j = 0; j < PER_THREAD; j++) {
        int e = base_e + threadIdx.x + j * 256;
        e_j[j] = e;
        if (e < n_edges) {
            int t = __ldg(&edge_type[e]);
            t_j[j] = t;
            r_j[j] = __ldg(&rij[e]);
            rank_j[j] = atomicAdd(&s_cnt[t], 1);
        } else {
            t_j[j] = -1;
        }
    }
    __syncthreads();
    if (threadIdx.x < N_BOND_TYPES && s_cnt[threadIdx.x] != 0)
        s_base[threadIdx.x] = atomicAdd(&g_cursor[threadIdx.x], s_cnt[threadIdx.x]);
    __syncthreads();

    #pragma unroll
    for (int j = 0; j < PER_THREAD; j++) {
        if (t_j[j] >= 0) {
            int pos = s_base[t_j[j]] + rank_j[j];
            int2 rec;
            rec.x = e_j[j] | (t_j[j] << 24);
            rec.y = __float_as_int(r_j[j]);
            g_sorted[pos] = rec;
        }
    }
}

// ---------------------------------------------------------------------------
// K4: per-chunk edge interpolation with the full 64KB type slice staged in
// shared memory (LDS 29cyc fixed latency, zero L2 table traffic).
// 4 threads per edge. Trailing blocks do the node gather.
// ---------------------------------------------------------------------------
__global__ void __launch_bounds__(256) k4_edges_nodes(
    float*       __restrict__ out,
    const int*   __restrict__ atom_type,
    const float* __restrict__ onsiteE,
    int n_edges, int n_nodes, int edge_blocks)
{
    extern __shared__ float smem[];
    if (blockIdx.x < edge_blocks) {
        int4 d = g_chunks[blockIdx.x];
        int t = d.x;
        if (t < 0) return;

        float* s_hop = smem;                 // [512][16]
        float* s_ovl = smem + SLICE_ELEMS;

        // Stage the type slice: 2 x 2048 coalesced float4 loads (L2-resident)
        {
            const float4* hs = (const float4*)(g_hopT + (size_t)t * SLICE_ELEMS);
            const float4* os = (const float4*)(g_ovlT + (size_t)t * SLICE_ELEMS);
            float4* sh4 = (float4*)s_hop;
            float4* so4 = (float4*)s_ovl;
            #pragma unroll
            for (int i = threadIdx.x; i < SLICE_ELEMS / 4; i += 256) {
                sh4[i] = __ldg(hs + i);
                so4[i] = __ldg(os + i);
            }
        }
        __syncthreads();

        int s = threadIdx.x >> 2;       // edge slot within 64-edge group
        int q = threadIdx.x & 3;        // quartet index
        int qo = q * 4;
        const size_t edge_out_elems = (size_t)n_edges * NUM_INGRLS;
        float4* out_h = (float4*)out;
        float4* out_o = (float4*)(out + edge_out_elems);

        int iters = (d.z + 63) >> 6;
        #pragma unroll 2
        for (int it = 0; it < iters; it++) {
            int li = it * 64 + s;
            if (li < d.z) {
                int2 rec = __ldg(&g_sorted[d.y + li]);
                int e = rec.x & 0xFFFFFF;
                float r = __int_as_float(rec.y);

                float tt = (r - X0_C) * (1.0f / DX_C);
                int i0 = (int)floorf(tt);
                i0 = min(max(i0, 0), NGRID - 2);
                float frac = tt - (float)i0;
                float omf  = 1.0f - frac;

                int ro = i0 * NUM_INGRLS + qo;
                float4 h0 = *(const float4*)(s_hop + ro);
                float4 h1 = *(const float4*)(s_hop + ro + NUM_INGRLS);
                float4 o0 = *(const float4*)(s_ovl + ro);
                float4 o1 = *(const float4*)(s_ovl + ro + NUM_INGRLS);

                float4 hv, ov;
                hv.x = h0.x * omf + h1.x * frac;
                hv.y = h0.y * omf + h1.y * frac;
                hv.z = h0.z * omf + h1.z * frac;
                hv.w = h0.w * omf + h1.w * frac;
                ov.x = o0.x * omf + o1.x * frac;
                ov.y = o0.y * omf + o1.y * frac;
                ov.z = o0.z * omf + o1.z * frac;
                ov.w = o0.w * omf + o1.w * frac;

                size_t oidx = (size_t)e * 4 + q;
                out_h[oidx] = hv;
                out_o[oidx] = ov;
            }
        }
    } else {
        // Node gather: 4 nodes per thread
        int tthr = (blockIdx.x - edge_blocks) * 256 + threadIdx.x;
        int n0 = tthr * 4;
        if (n0 >= n_nodes) return;
        const float4* on = (const float4*)onsiteE;
        float4* outv = (float4*)(out + 2 * (size_t)n_edges * NUM_INGRLS);
        if (n0 + 4 <= n_nodes) {
            int4 a = __ldg((const int4*)atom_type + tthr);
            float4 v0 = __ldg(on + a.x);
            float4 v1 = __ldg(on + a.y);
            float4 v2 = __ldg(on + a.z);
            float4 v3 = __ldg(on + a.w);
            outv[n0 + 0] = v0;
            outv[n0 + 1] = v1;
            outv[n0 + 2] = v2;
            outv[n0 + 3] = v3;
        } else {
            for (int n = n0; n < n_nodes; n++) {
                int a = __ldg(&atom_type[n]);
                outv[n] = __ldg(on + a);
            }
        }
    }
}

extern "C" void kernel_launch(void* const* d_in, const int* in_sizes, int n_in,
                              void* d_out, int out_size)
{
    const float* rij            = (const float*)d_in[0];
    const int*   edge_type      = (const int*)  d_in[1];
    const int*   atom_type      = (const int*)  d_in[2];
    const float* hopping_tables = (const float*)d_in[3];
    const float* overlap_tables = (const float*)d_in[4];
    const float* onsiteE        = (const float*)d_in[5];
    float*       out            = (float*)d_out;

    int n_edges = in_sizes[0];
    int n_nodes = in_sizes[2];

    int bin_blocks   = (n_edges + EPB - 1) / EPB;
    int chunk_blocks = bin_blocks + N_BOND_TYPES;     // worst-case fragmentation
    if (chunk_blocks > MAX_CHUNKS) chunk_blocks = MAX_CHUNKS;
    int node_blocks  = (n_nodes + 256 * 4 - 1) / (256 * 4);

    // Opt into 64KB dynamic smem for K4 (idempotent; host-side, not captured)
    cudaFuncSetAttribute(k4_edges_nodes,
                         cudaFuncAttributeMaxDynamicSharedMemorySize, SMEM_BYTES);

    k1_transpose_hist<<<TRANS_BLOCKS + HIST_BLOCKS, 256>>>(
        hopping_tables, overlap_tables, edge_type, n_edges);
    k2_scan_chunks<<<1, 32>>>(chunk_blocks);
    k3_scatter<<<bin_blocks, 256>>>(rij, edge_type, n_edges);
    k4_edges_nodes<<<chunk_blocks + node_blocks, 256, SMEM_BYTES>>>(
        out, atom_type, onsiteE, n_edges, n_nodes, chunk_blocks);
}

// round 13
// speedup vs baseline: 1.3156x; 1.3156x over previous
#include <cuda_runtime.h>
#include <cuda_bf16.h>
#include <cstdint>

// Problem constants (match reference)
#define NGRID        512
#define X0_C         1.0f
#define XMAX_C       10.0f
#define DX_C         ((XMAX_C - X0_C) / (float)(NGRID - 1))   // 9/511
#define N_BOND_TYPES 10
#define NUM_INGRLS   16
#define E_MAX        2000000

#define TRANS_BLOCKS 320          // 163840 elems / 512
#define HIST_BLOCKS  592
#define EPB          2048         // edges per scatter block

#define SLICE_ELEMS  (NGRID * NUM_INGRLS)   // 8192 floats = 32KB per type/table

// Transposed tables: [B][G][16] -> one (b,i0) row = 64B contiguous.
__device__ float g_hopT[N_BOND_TYPES * SLICE_ELEMS];
__device__ float g_ovlT[N_BOND_TYPES * SLICE_ELEMS];

// Binning state + sorted edge records: (e | type<<24, rij_bits)
__device__ int  g_hist[N_BOND_TYPES];      // zero-init; re-zeroed by K2 each run
__device__ int  g_cursor[N_BOND_TYPES];
__device__ int2 g_sorted[E_MAX];

// ---------------------------------------------------------------------------
// K1: table transpose (blocks [0,320)) + edge-type histogram (rest)
// ---------------------------------------------------------------------------
__global__ void __launch_bounds__(256) k1_transpose_hist(
    const float* __restrict__ hopping_tables,
    const float* __restrict__ overlap_tables,
    const int*   __restrict__ edge_type,
    int n_edges)
{
    if (blockIdx.x < TRANS_BLOCKS) {
        int idx = blockIdx.x * blockDim.x + threadIdx.x;
        const int total = N_BOND_TYPES * NUM_INGRLS * NGRID;
        if (idx >= total) return;
        int g  = idx & (NGRID - 1);
        int bm = idx >> 9;
        int m  = bm & (NUM_INGRLS - 1);
        int b  = bm >> 4;
        int dst = (b * NGRID + g) * NUM_INGRLS + m;
        g_hopT[dst] = hopping_tables[idx];
        g_ovlT[dst] = overlap_tables[idx];
    } else {
        __shared__ int s_cnt[N_BOND_TYPES];
        if (threadIdx.x < N_BOND_TYPES) s_cnt[threadIdx.x] = 0;
        __syncthreads();
        int nb = gridDim.x - TRANS_BLOCKS;
        int start = (blockIdx.x - TRANS_BLOCKS) * 256 + threadIdx.x;
        int stride = nb * 256;
        for (int e = start; e < n_edges; e += stride) {
            int t = __ldg(&edge_type[e]);
            atomicAdd(&s_cnt[t], 1);
        }
        __syncthreads();
        if (threadIdx.x < N_BOND_TYPES && s_cnt[threadIdx.x] != 0)
            atomicAdd(&g_hist[threadIdx.x], s_cnt[threadIdx.x]);
    }
}

// ---------------------------------------------------------------------------
// K2: warp scan of histogram -> bin cursors; re-zero histogram for replay.
// ---------------------------------------------------------------------------
__global__ void k2_scan()
{
    int lane = threadIdx.x;   // 32 threads
    int cnt = (lane < N_BOND_TYPES) ? g_hist[lane] : 0;
    int s = cnt;
    #pragma unroll
    for (int d = 1; d < 32; d <<= 1) {
        int v = __shfl_up_sync(0xFFFFFFFFu, s, d);
        if (lane >= d) s += v;
    }
    if (lane < N_BOND_TYPES) {
        g_cursor[lane] = s - cnt;
        g_hist[lane] = 0;
    }
}

// ---------------------------------------------------------------------------
// K3: counting-sort scatter. One global atomic per (block,type); records
// (e|t<<24, rij_bits). Order within a bin is non-deterministic but every
// edge writes its own output slot later -> output deterministic.
// ---------------------------------------------------------------------------
__global__ void __launch_bounds__(256) k3_scatter(
    const float* __restrict__ rij,
    const int*   __restrict__ edge_type,
    int n_edges)
{
    __shared__ int s_cnt[N_BOND_TYPES];
    __shared__ int s_base[N_BOND_TYPES];
    if (threadIdx.x < N_BOND_TYPES) s_cnt[threadIdx.x] = 0;
    __syncthreads();

    const int PER_THREAD = EPB / 256;   // 8
    int base_e = blockIdx.x * EPB;

    int   t_j[PER_THREAD];
    int   rank_j[PER_THREAD];
    int   e_j[PER_THREAD];
    float r_j[PER_THREAD];

    #pragma unroll
    for (int j = 0; j < PER_THREAD; j++) {
        int e = base_e + threadIdx.x + j * 256;
        e_j[j] = e;
        if (e < n_edges) {
            int t = __ldg(&edge_type[e]);
            t_j[j] = t;
            r_j[j] = __ldg(&rij[e]);
            rank_j[j] = atomicAdd(&s_cnt[t], 1);
        } else {
            t_j[j] = -1;
        }
    }
    __syncthreads();
    if (threadIdx.x < N_BOND_TYPES && s_cnt[threadIdx.x] != 0)
        s_base[threadIdx.x] = atomicAdd(&g_cursor[threadIdx.x], s_cnt[threadIdx.x]);
    __syncthreads();

    #pragma unroll
    for (int j = 0; j < PER_THREAD; j++) {
        if (t_j[j] >= 0) {
            int pos = s_base[t_j[j]] + rank_j[j];
            int2 rec;
            rec.x = e_j[j] | (t_j[j] << 24);
            rec.y = __float_as_int(r_j[j]);
            g_sorted[pos] = rec;
        }
    }
}

// ---------------------------------------------------------------------------
// K4: FLAT one-thread-per-quartet over the SORTED records (R2 structure,
// binned locality). Consecutive threads share one bond type -> the ~64KB
// type slice is L1-resident; table gathers are L1 hits, L2 sees only cold
// misses. Stores go to the edge's original slot (64B chunks = same L2
// sector count as dense). Trailing blocks do the node gather.
// ---------------------------------------------------------------------------
__global__ void __launch_bounds__(256) k4_edges_nodes(
    float*       __restrict__ out,
    const int*   __restrict__ atom_type,
    const float* __restrict__ onsiteE,
    int n_edges, int n_nodes, int edge_blocks)
{
    if (blockIdx.x < edge_blocks) {
        int idx = blockIdx.x * 256 + threadIdx.x;   // [0, n_edges*4)
        int p = idx >> 2;
        if (p >= n_edges) return;
        int q = idx & 3;

        int2 rec = __ldg(&g_sorted[p]);
        int e = rec.x & 0xFFFFFF;
        int t = rec.x >> 24;
        float r = __int_as_float(rec.y);

        float tt = (r - X0_C) * (1.0f / DX_C);
        int i0 = (int)floorf(tt);
        i0 = min(max(i0, 0), NGRID - 2);
        float frac = tt - (float)i0;
        float omf  = 1.0f - frac;

        size_t row = (size_t)(t * NGRID + i0) * (NUM_INGRLS / 4);  // float4 units
        const float4* hrow = (const float4*)g_hopT + row;
        const float4* orow = (const float4*)g_ovlT + row;

        float4 h0 = __ldg(hrow + q);
        float4 h1 = __ldg(hrow + 4 + q);
        float4 o0 = __ldg(orow + q);
        float4 o1 = __ldg(orow + 4 + q);

        float4 hv, ov;
        hv.x = h0.x * omf + h1.x * frac;
        hv.y = h0.y * omf + h1.y * frac;
        hv.z = h0.z * omf + h1.z * frac;
        hv.w = h0.w * omf + h1.w * frac;
        ov.x = o0.x * omf + o1.x * frac;
        ov.y = o0.y * omf + o1.y * frac;
        ov.z = o0.z * omf + o1.z * frac;
        ov.w = o0.w * omf + o1.w * frac;

        float4* out_h = (float4*)out;
        float4* out_o = (float4*)(out + (size_t)n_edges * NUM_INGRLS);
        size_t oidx = (size_t)e * 4 + q;
        out_h[oidx] = hv;
        out_o[oidx] = ov;
    } else {
        // Node gather: 4 nodes per thread
        int tthr = (blockIdx.x - edge_blocks) * 256 + threadIdx.x;
        int n0 = tthr * 4;
        if (n0 >= n_nodes) return;
        const float4* on = (const float4*)onsiteE;
        float4* outv = (float4*)(out + 2 * (size_t)n_edges * NUM_INGRLS);
        if (n0 + 4 <= n_nodes) {
            int4 a = __ldg((const int4*)atom_type + tthr);
            float4 v0 = __ldg(on + a.x);
            float4 v1 = __ldg(on + a.y);
            float4 v2 = __ldg(on + a.z);
            float4 v3 = __ldg(on + a.w);
            outv[n0 + 0] = v0;
            outv[n0 + 1] = v1;
            outv[n0 + 2] = v2;
            outv[n0 + 3] = v3;
        } else {
            for (int n = n0; n < n_nodes; n++) {
                int a = __ldg(&atom_type[n]);
                outv[n] = __ldg(on + a);
            }
        }
    }
}

extern "C" void kernel_launch(void* const* d_in, const int* in_sizes, int n_in,
                              void* d_out, int out_size)
{
    const float* rij            = (const float*)d_in[0];
    const int*   edge_type      = (const int*)  d_in[1];
    const int*   atom_type      = (const int*)  d_in[2];
    const float* hopping_tables = (const float*)d_in[3];
    const float* overlap_tables = (const float*)d_in[4];
    const float* onsiteE        = (const float*)d_in[5];
    float*       out            = (float*)d_out;

    int n_edges = in_sizes[0];
    int n_nodes = in_sizes[2];

    int scatter_blocks = (n_edges + EPB - 1) / EPB;
    int edge_blocks    = (n_edges * 4 + 255) / 256;
    int node_blocks    = (n_nodes + 256 * 4 - 1) / (256 * 4);

    k1_transpose_hist<<<TRANS_BLOCKS + HIST_BLOCKS, 256>>>(
        hopping_tables, overlap_tables, edge_type, n_edges);
    k2_scan<<<1, 32>>>();
    k3_scatter<<<scatter_blocks, 256>>>(rij, edge_type, n_edges);
    k4_edges_nodes<<<edge_blocks + node_blocks, 256>>>(
        out, atom_type, onsiteE, n_edges, n_nodes, edge_blocks);
}